// round 16
// baseline (speedup 1.0000x reference)
#include <cuda_runtime.h>

#define BB 16
#define NN 1024
#define DD 1024   // D2H
#define UU 512
#define TOK (BB * NN)

#define DGRP 4                      // d-groups of 256
#define UCH  128                    // u-chunks
#define UC   (UU / UCH)             // 4 u per chunk
#define PRO  (DGRP * UCH)           // 512 prologue blocks

#define ROW_BLOCKS (TOK / 16)       // 1024 (16 rows per block, warp per 2 rows)
#define OUT_BLOCKS (TOK / 8)        // 2048 (8 rows per block)
#define RB_PER_BATCH (NN / 16)      // 64 producer blocks per batch

// Scratch (no device allocation allowed; rewritten every launch).
__device__ float g_ph[UCH * DD];
__device__ float g_pm[UCH * DD];
__device__ float g_vh[DD];
__device__ float g_vm[DD];
__device__ float g_const;
__device__ float g_sH[TOK];
__device__ float g_sM[TOK];
__device__ int   g_done[BB];

// ---------------------------------------------------------------------------
// Stage 1: v partials.  512 blocks x 256 threads, 4 u's each — k_pre is
// ramp/tail dominated, so maximize SM coverage (128->256 blocks already
// gave 6.0->5.3us; this continues the trend).  Block 0 zeroes g_done.
// ---------------------------------------------------------------------------
__global__ void k_pre(const float* __restrict__ Wh,
                      const float* __restrict__ Wm,
                      const float* __restrict__ wout) {
    int t = threadIdx.x;
    if (blockIdx.x == 0 && t < BB) g_done[t] = 0;

    int d  = (blockIdx.x & (DGRP - 1)) * 256 + t;
    int uc = blockIdx.x >> 2;               // / DGRP, 0..127
    int u0 = uc * UC;
    float ah = 0.f, am = 0.f;
#pragma unroll
    for (int i = 0; i < UC; ++i) {
        float w = __ldg(&wout[u0 + i]);
        ah = fmaf(Wh[(size_t)(u0 + i) * DD + d], w, ah);
        am = fmaf(Wm[(size_t)(u0 + i) * DD + d], w, am);
    }
    g_ph[uc * DD + d] = ah;
    g_pm[uc * DD + d] = am;
}

// ---------------------------------------------------------------------------
// Stage 2: blocks 0..3 fold the 128 partials into v_h/v_m (256 d each);
// block 4 computes g_const = (b_h + b_m) . w_out + b_out.
// ---------------------------------------------------------------------------
__global__ void k_finish(const float* __restrict__ bh,
                         const float* __restrict__ bm,
                         const float* __restrict__ wout,
                         const float* __restrict__ bout) {
    int t = threadIdx.x;
    if (blockIdx.x < 4) {
        int d = blockIdx.x * 256 + t;
        float ah = 0.f, am = 0.f;
#pragma unroll 16
        for (int c = 0; c < UCH; ++c) {
            ah += g_ph[c * DD + d];
            am += g_pm[c * DD + d];
        }
        g_vh[d] = ah;
        g_vm[d] = am;
    } else {
        __shared__ float red[8];
        float acc = (bh[t] + bm[t]) * wout[t]
                  + (bh[t + 256] + bm[t + 256]) * wout[t + 256];
#pragma unroll
        for (int o = 16; o > 0; o >>= 1)
            acc += __shfl_down_sync(0xffffffffu, acc, o);
        if ((t & 31) == 0) red[t >> 5] = acc;
        __syncthreads();
        if (t < 8) {
            acc = red[t];
#pragma unroll
            for (int o = 4; o > 0; o >>= 1)
                acc += __shfl_down_sync(0x000000ffu, acc, o);
            if (t == 0) g_const = acc + bout[0];
        }
    }
}

// ---------------------------------------------------------------------------
// Stage 3 (fused row+out pipeline) — byte-identical to the proven best
// (R7/R14): __ldcs streaming producer, warp per 2 rows; __stcs batch-gated
// 8-row consumer.
// ---------------------------------------------------------------------------
__global__ void __launch_bounds__(256, 3)
k_main(const float* __restrict__ x, float* __restrict__ out) {
    int bid = blockIdx.x;
    int t   = threadIdx.x;

    if (bid < ROW_BLOCKS) {
        // ---- producer: 2 rows per warp, 16 rows per block ----
        int warp = t >> 5;
        int lane = t & 31;
        int r0   = bid * 16 + warp * 2;     // rows r0, r0+1
        const float4* x0  = reinterpret_cast<const float4*>(x + (size_t)r0 * DD);
        const float4* x1  = x0 + (DD / 4);
        const float4* vh4 = reinterpret_cast<const float4*>(g_vh);
        const float4* vm4 = reinterpret_cast<const float4*>(g_vm);

        float4 xa[8], xb[8];
#pragma unroll
        for (int i = 0; i < 8; ++i) xa[i] = __ldcs(&x0[lane + 32 * i]);
#pragma unroll
        for (int i = 0; i < 8; ++i) xb[i] = __ldcs(&x1[lane + 32 * i]);

        float ah0 = 0.f, am0 = 0.f, ah1 = 0.f, am1 = 0.f;
#pragma unroll
        for (int i = 0; i < 8; ++i) {
            int idx = lane + 32 * i;
            float4 h = vh4[idx];
            float4 m = vm4[idx];
            ah0 = fmaf(xa[i].x, h.x, fmaf(xa[i].y, h.y, fmaf(xa[i].z, h.z, fmaf(xa[i].w, h.w, ah0))));
            am0 = fmaf(xa[i].x, m.x, fmaf(xa[i].y, m.y, fmaf(xa[i].z, m.z, fmaf(xa[i].w, m.w, am0))));
            ah1 = fmaf(xb[i].x, h.x, fmaf(xb[i].y, h.y, fmaf(xb[i].z, h.z, fmaf(xb[i].w, h.w, ah1))));
            am1 = fmaf(xb[i].x, m.x, fmaf(xb[i].y, m.y, fmaf(xb[i].z, m.z, fmaf(xb[i].w, m.w, am1))));
        }
#pragma unroll
        for (int o = 16; o > 0; o >>= 1) {
            ah0 += __shfl_xor_sync(0xffffffffu, ah0, o);
            am0 += __shfl_xor_sync(0xffffffffu, am0, o);
            ah1 += __shfl_xor_sync(0xffffffffu, ah1, o);
            am1 += __shfl_xor_sync(0xffffffffu, am1, o);
        }
        if (lane == 0) {
            g_sH[r0]     = ah0;
            g_sH[r0 + 1] = ah1;
            g_sM[r0]     = am0;
            g_sM[r0 + 1] = am1;
            __threadfence();                        // release
        }
        __syncthreads();
        if (t == 0) atomicAdd(&g_done[bid >> 6], 1);   // RB_PER_BATCH = 64
    } else {
        // ---- consumer: write 8 output rows of one batch ----
        int ob = bid - ROW_BLOCKS;
        int i0 = ob * 8;            // global row base (b*NN + i)
        int b  = i0 >> 10;          // NN = 1024

        if (t == 0) {
            while (*(volatile int*)&g_done[b] < RB_PER_BATCH)
                __nanosleep(128);
            __threadfence();        // acquire
        }
        __syncthreads();

        float4 m = reinterpret_cast<const float4*>(g_sM + (size_t)b * NN)[t];
        float  c = g_const;
        float4 h0 = reinterpret_cast<const float4*>(g_sH + i0)[0];
        float4 h1 = reinterpret_cast<const float4*>(g_sH + i0)[1];
        float base[8] = {h0.x + c, h0.y + c, h0.z + c, h0.w + c,
                         h1.x + c, h1.y + c, h1.z + c, h1.w + c};
#pragma unroll
        for (int r = 0; r < 8; ++r) {
            __stcs(reinterpret_cast<float4*>(out + (size_t)(i0 + r) * NN) + t,
                   make_float4(base[r] + m.x, base[r] + m.y,
                               base[r] + m.z, base[r] + m.w));
        }
    }
}

extern "C" void kernel_launch(void* const* d_in, const int* in_sizes, int n_in,
                              void* d_out, int out_size) {
    const float* x    = (const float*)d_in[0];
    const float* Wh   = (const float*)d_in[1];
    const float* bh   = (const float*)d_in[2];
    const float* Wm   = (const float*)d_in[3];
    const float* bm   = (const float*)d_in[4];
    const float* wout = (const float*)d_in[5];
    const float* bout = (const float*)d_in[6];
    float* out = (float*)d_out;

    k_pre<<<PRO, 256>>>(Wh, Wm, wout);
    k_finish<<<5, 256>>>(bh, bm, wout, bout);
    k_main<<<ROW_BLOCKS + OUT_BLOCKS, 256>>>(x, out);
}

// round 17
// speedup vs baseline: 1.2757x; 1.2757x over previous
#include <cuda_runtime.h>

#define BB 16
#define NN 1024
#define DD 1024   // D2H
#define UU 512
#define TOK (BB * NN)

#define DGRP 4                      // d-groups of 256
#define UCH  64                     // u-chunks
#define UC   (UU / UCH)             // 8 u per chunk
#define PRO  (DGRP * UCH)           // 256 prologue blocks (proven 5.3us)

#define ROW_BLOCKS (TOK / 16)       // 1024 (16 rows per block, warp per 2 rows)
#define OUT_BLOCKS (TOK / 8)        // 2048 (8 rows per block)
#define RB_PER_BATCH (NN / 16)      // 64 producer blocks per batch

// Scratch (no device allocation allowed; rewritten every launch).
__device__ float g_ph[UCH * DD];
__device__ float g_pm[UCH * DD];
__device__ float g_vh[DD];
__device__ float g_vm[DD];
__device__ float g_const;
__device__ float g_sH[TOK];
__device__ float g_sM[TOK];
__device__ int   g_done[BB];

// ---------------------------------------------------------------------------
// Stage 1: v partials — proven best geometry (256 blocks x 256 threads,
// 8 u's per thread; measured 5.3-5.4us across three rounds).
// Block 0 zeroes the g_done counters for this replay.
// ---------------------------------------------------------------------------
__global__ void k_pre(const float* __restrict__ Wh,
                      const float* __restrict__ Wm,
                      const float* __restrict__ wout) {
    int t = threadIdx.x;
    if (blockIdx.x == 0 && t < BB) g_done[t] = 0;

    int d  = (blockIdx.x & (DGRP - 1)) * 256 + t;
    int uc = blockIdx.x >> 2;               // / DGRP, 0..63
    int u0 = uc * UC;
    float ah = 0.f, am = 0.f;
#pragma unroll
    for (int i = 0; i < UC; ++i) {
        float w = __ldg(&wout[u0 + i]);
        ah = fmaf(Wh[(size_t)(u0 + i) * DD + d], w, ah);
        am = fmaf(Wm[(size_t)(u0 + i) * DD + d], w, am);
    }
    g_ph[uc * DD + d] = ah;
    g_pm[uc * DD + d] = am;
}

// ---------------------------------------------------------------------------
// Stage 2: blocks 0..3 fold the 64 partials into v_h/v_m (256 d each);
// block 4 computes g_const = (b_h + b_m) . w_out + b_out.  (Proven.)
// ---------------------------------------------------------------------------
__global__ void k_finish(const float* __restrict__ bh,
                         const float* __restrict__ bm,
                         const float* __restrict__ wout,
                         const float* __restrict__ bout) {
    int t = threadIdx.x;
    if (blockIdx.x < 4) {
        int d = blockIdx.x * 256 + t;
        float ah = 0.f, am = 0.f;
#pragma unroll
        for (int c = 0; c < UCH; ++c) {
            ah += g_ph[c * DD + d];
            am += g_pm[c * DD + d];
        }
        g_vh[d] = ah;
        g_vm[d] = am;
    } else {
        __shared__ float red[8];
        float acc = (bh[t] + bm[t]) * wout[t]
                  + (bh[t + 256] + bm[t + 256]) * wout[t + 256];
#pragma unroll
        for (int o = 16; o > 0; o >>= 1)
            acc += __shfl_down_sync(0xffffffffu, acc, o);
        if ((t & 31) == 0) red[t >> 5] = acc;
        __syncthreads();
        if (t < 8) {
            acc = red[t];
#pragma unroll
            for (int o = 4; o > 0; o >>= 1)
                acc += __shfl_down_sync(0x000000ffu, acc, o);
            if (t == 0) g_const = acc + bout[0];
        }
    }
}

// ---------------------------------------------------------------------------
// Stage 3 (fused row+out pipeline) — byte-identical to the best-measured
// kernel (R7, 35.39us): __ldcs streaming producer (warp per 2 rows, 16
// prefetched float4s, shared v loads), __stcs batch-gated 8-row consumer.
// ---------------------------------------------------------------------------
__global__ void __launch_bounds__(256, 3)
k_main(const float* __restrict__ x, float* __restrict__ out) {
    int bid = blockIdx.x;
    int t   = threadIdx.x;

    if (bid < ROW_BLOCKS) {
        // ---- producer: 2 rows per warp, 16 rows per block ----
        int warp = t >> 5;
        int lane = t & 31;
        int r0   = bid * 16 + warp * 2;     // rows r0, r0+1
        const float4* x0  = reinterpret_cast<const float4*>(x + (size_t)r0 * DD);
        const float4* x1  = x0 + (DD / 4);
        const float4* vh4 = reinterpret_cast<const float4*>(g_vh);
        const float4* vm4 = reinterpret_cast<const float4*>(g_vm);

        float4 xa[8], xb[8];
#pragma unroll
        for (int i = 0; i < 8; ++i) xa[i] = __ldcs(&x0[lane + 32 * i]);
#pragma unroll
        for (int i = 0; i < 8; ++i) xb[i] = __ldcs(&x1[lane + 32 * i]);

        float ah0 = 0.f, am0 = 0.f, ah1 = 0.f, am1 = 0.f;
#pragma unroll
        for (int i = 0; i < 8; ++i) {
            int idx = lane + 32 * i;
            float4 h = vh4[idx];
            float4 m = vm4[idx];
            ah0 = fmaf(xa[i].x, h.x, fmaf(xa[i].y, h.y, fmaf(xa[i].z, h.z, fmaf(xa[i].w, h.w, ah0))));
            am0 = fmaf(xa[i].x, m.x, fmaf(xa[i].y, m.y, fmaf(xa[i].z, m.z, fmaf(xa[i].w, m.w, am0))));
            ah1 = fmaf(xb[i].x, h.x, fmaf(xb[i].y, h.y, fmaf(xb[i].z, h.z, fmaf(xb[i].w, h.w, ah1))));
            am1 = fmaf(xb[i].x, m.x, fmaf(xb[i].y, m.y, fmaf(xb[i].z, m.z, fmaf(xb[i].w, m.w, am1))));
        }
#pragma unroll
        for (int o = 16; o > 0; o >>= 1) {
            ah0 += __shfl_xor_sync(0xffffffffu, ah0, o);
            am0 += __shfl_xor_sync(0xffffffffu, am0, o);
            ah1 += __shfl_xor_sync(0xffffffffu, ah1, o);
            am1 += __shfl_xor_sync(0xffffffffu, am1, o);
        }
        if (lane == 0) {
            g_sH[r0]     = ah0;
            g_sH[r0 + 1] = ah1;
            g_sM[r0]     = am0;
            g_sM[r0 + 1] = am1;
            __threadfence();                        // release
        }
        __syncthreads();
        if (t == 0) atomicAdd(&g_done[bid >> 6], 1);   // RB_PER_BATCH = 64
    } else {
        // ---- consumer: write 8 output rows of one batch ----
        int ob = bid - ROW_BLOCKS;
        int i0 = ob * 8;            // global row base (b*NN + i)
        int b  = i0 >> 10;          // NN = 1024

        if (t == 0) {
            while (*(volatile int*)&g_done[b] < RB_PER_BATCH)
                __nanosleep(128);
            __threadfence();        // acquire
        }
        __syncthreads();

        float4 m = reinterpret_cast<const float4*>(g_sM + (size_t)b * NN)[t];
        float  c = g_const;
        float4 h0 = reinterpret_cast<const float4*>(g_sH + i0)[0];
        float4 h1 = reinterpret_cast<const float4*>(g_sH + i0)[1];
        float base[8] = {h0.x + c, h0.y + c, h0.z + c, h0.w + c,
                         h1.x + c, h1.y + c, h1.z + c, h1.w + c};
#pragma unroll
        for (int r = 0; r < 8; ++r) {
            __stcs(reinterpret_cast<float4*>(out + (size_t)(i0 + r) * NN) + t,
                   make_float4(base[r] + m.x, base[r] + m.y,
                               base[r] + m.z, base[r] + m.w));
        }
    }
}

extern "C" void kernel_launch(void* const* d_in, const int* in_sizes, int n_in,
                              void* d_out, int out_size) {
    const float* x    = (const float*)d_in[0];
    const float* Wh   = (const float*)d_in[1];
    const float* bh   = (const float*)d_in[2];
    const float* Wm   = (const float*)d_in[3];
    const float* bm   = (const float*)d_in[4];
    const float* wout = (const float*)d_in[5];
    const float* bout = (const float*)d_in[6];
    float* out = (float*)d_out;

    k_pre<<<PRO, 256>>>(Wh, Wm, wout);
    k_finish<<<5, 256>>>(bh, bm, wout, bout);
    k_main<<<ROW_BLOCKS + OUT_BLOCKS, 256>>>(x, out);
}